// round 6
// baseline (speedup 1.0000x reference)
#include <cuda_runtime.h>
#include <cstdint>

#define BATCH 8
#define SEQ   2048
#define EDIM  1024
#define HDIM  128

#define NEG_INF (__int_as_float(0xff800000))

#define KCHUNK 512            // split-K chunk for PV
#define NCHUNK 4              // max chunks (2048/512)
#define TCH    8              // t-chunks for stats (2048/256)

typedef unsigned long long u64;

// ---------------- packed fp32x2 helpers (sm_100+ PTX) ------------------------
__device__ __forceinline__ u64 pack_dup_f32(float x) {
    u64 d;
    unsigned int xi = __float_as_uint(x);
    asm("mov.b64 %0, {%1, %2};" : "=l"(d) : "r"(xi), "r"(xi));
    return d;
}
__device__ __forceinline__ void fma_f32x2(u64& d, u64 a, u64 b) {
    asm("fma.rn.f32x2 %0, %1, %2, %3;" : "=l"(d) : "l"(a), "l"(b), "l"(d));
}
__device__ __forceinline__ void unpack_f32x2(u64 v, float& lo, float& hi) {
    unsigned int l32, h32;
    asm("mov.b64 {%0, %1}, %2;" : "=r"(l32), "=r"(h32) : "l"(v));
    lo = __uint_as_float(l32);
    hi = __uint_as_float(h32);
}

// ---------------- scratch (device globals; no allocation allowed) ------------
__device__ float g_q[BATCH * SEQ * HDIM];
__device__ float g_k[BATCH * SEQ * HDIM];
__device__ float g_v[BATCH * SEQ * HDIM];
__device__ float g_S[(size_t)BATCH * SEQ * SEQ];          // 134 MB (upper triangle untouched)
__device__ float g_pm[BATCH * TCH * SEQ];                 // stats partials (max)
__device__ float g_pl[BATCH * TCH * SEQ];                 // stats partials (sum)
__device__ float g_m[BATCH * SEQ];
__device__ float g_rl[BATCH * SEQ];
__device__ float g_Op[NCHUNK][BATCH * SEQ * HDIM];        // PV split-K partials (33.5 MB)

// =============================================================================
// Inner product over one k-tile: 8x8 register tile held as 8x4 packed f32x2
// pairs (pairs along the column/j axis). A operand comes from smem ALREADY
// duplicated into both 32-bit lanes (As2, u64 per element); B pairs are
// contiguous floats loaded as u64. 44 issues per kk for 128 FMAs.
// =============================================================================
#define GEMM_INNER(AS2, BS, TRR, TCC)                                           \
    _Pragma("unroll")                                                           \
    for (int kk = 0; kk < 8; kk++) {                                            \
        u64 rb2[4];                                                             \
        _Pragma("unroll")                                                       \
        for (int j = 0; j < 4; j++)                                             \
            rb2[j] = *(const u64*)(&BS[kk][(TCC) * 8 + j * 2]);                 \
        _Pragma("unroll")                                                       \
        for (int i = 0; i < 8; i++) {                                           \
            const u64 ra2 = AS2[kk][(TRR) * 8 + i];                             \
            _Pragma("unroll")                                                   \
            for (int j = 0; j < 4; j++)                                         \
                fma_f32x2(acc2[i][j], ra2, rb2[j]);                             \
        }                                                                       \
    }

// =============================================================================
// Kernel A: QKV projection.  Y = X @ W  for W in {Wk, Wq, Wv}
// M = B*T = 16384, K = E = 1024, N = H = 128.
// 128x128x8 SGEMM, 256 threads, 8x8 register tile, double-buffered smem,
// packed FFMA2 math with pre-duplicated A operand.  grid = (M/128, 1, 3)
// =============================================================================
__global__ void __launch_bounds__(256, 2) qkv_gemm(const float* __restrict__ X,
                                                   const float* __restrict__ Wk,
                                                   const float* __restrict__ Wq,
                                                   const float* __restrict__ Wv) {
    const float* W;
    float* Y;
    if (blockIdx.z == 0)      { W = Wk; Y = g_k; }
    else if (blockIdx.z == 1) { W = Wq; Y = g_q; }
    else                      { W = Wv; Y = g_v; }

    __shared__ u64   As2[2][8][128];   // A, lane-duplicated (16 KB)
    __shared__ float Bs[2][8][128];    // B (8 KB)

    const int tid  = threadIdx.x;
    const int m0   = blockIdx.x * 128;
    const int tr   = tid / 16;
    const int tc   = tid % 16;
    const int arow = tid >> 1;           // 0..127
    const int acol = (tid & 1) * 4;      // 0 or 4
    const int b_r  = tid >> 5;           // 0..7
    const int b_c  = (tid & 31) * 4;     // 0..124

    u64 acc2[8][4] = {};                 // packed (col 2j, 2j+1)

    {
        float4 a = *(const float4*)(X + (size_t)(m0 + arow) * EDIM + acol);
        As2[0][acol + 0][arow] = pack_dup_f32(a.x);
        As2[0][acol + 1][arow] = pack_dup_f32(a.y);
        As2[0][acol + 2][arow] = pack_dup_f32(a.z);
        As2[0][acol + 3][arow] = pack_dup_f32(a.w);
        float4 b = *(const float4*)(W + (size_t)b_r * HDIM + b_c);
        *(float4*)(&Bs[0][b_r][b_c]) = b;
    }
    __syncthreads();

    int cur = 0;
    for (int ks = 0; ks < EDIM; ks += 8) {
        const int nxt = ks + 8;
        const bool more = nxt < EDIM;
        float4 a2, b2;
        if (more) {
            a2 = *(const float4*)(X + (size_t)(m0 + arow) * EDIM + nxt + acol);
            b2 = *(const float4*)(W + (size_t)(nxt + b_r) * HDIM + b_c);
        }

        GEMM_INNER(As2[cur], Bs[cur], tr, tc)

        if (more) {
            const int nb = cur ^ 1;
            As2[nb][acol + 0][arow] = pack_dup_f32(a2.x);
            As2[nb][acol + 1][arow] = pack_dup_f32(a2.y);
            As2[nb][acol + 2][arow] = pack_dup_f32(a2.z);
            As2[nb][acol + 3][arow] = pack_dup_f32(a2.w);
            *(float4*)(&Bs[nb][b_r][b_c]) = b2;
            __syncthreads();
            cur = nb;
        }
    }

#pragma unroll
    for (int i = 0; i < 8; i++) {
        const int m = m0 + tr * 8 + i;
#pragma unroll
        for (int j = 0; j < 4; j += 2) {
            float4 o;
            unpack_f32x2(acc2[i][j],     o.x, o.y);
            unpack_f32x2(acc2[i][j + 1], o.z, o.w);
            *(float4*)(Y + (size_t)m * HDIM + tc * 8 + j * 2) = o;
        }
    }
}

// =============================================================================
// Kernel B: S[b,t,s] = sqrt(H)*q[b,t].k[b,s] for s<=t; diagonal tile masks with
// -inf. Strictly-above-diagonal tiles are never written (and never read:
// pv reads columns s < t0+128 only; stats predicates on t>=s).
// grid = (T/128 s-tiles, T/128 t-tiles, B)
// =============================================================================
__global__ void __launch_bounds__(256, 2) scores_kernel() {
    const int b  = blockIdx.z;
    const int t0 = blockIdx.y * 128;
    const int s0 = blockIdx.x * 128;
    if (s0 > t0) return;

    float* S = g_S + (size_t)b * SEQ * SEQ;
    const float* Q = g_q + (size_t)b * SEQ * HDIM;
    const float* K = g_k + (size_t)b * SEQ * HDIM;

    __shared__ u64   As2[2][8][128];
    __shared__ float Bs[2][8][128];

    const int tid  = threadIdx.x;
    const int tr   = tid / 16;
    const int tc   = tid % 16;
    const int lrow = tid >> 1;
    const int lcol = (tid & 1) * 4;

    u64 acc2[8][4] = {};

    {
        float4 a = *(const float4*)(Q + (size_t)(t0 + lrow) * HDIM + lcol);
        As2[0][lcol + 0][lrow] = pack_dup_f32(a.x);
        As2[0][lcol + 1][lrow] = pack_dup_f32(a.y);
        As2[0][lcol + 2][lrow] = pack_dup_f32(a.z);
        As2[0][lcol + 3][lrow] = pack_dup_f32(a.w);
        float4 kb = *(const float4*)(K + (size_t)(s0 + lrow) * HDIM + lcol);
        Bs[0][lcol + 0][lrow] = kb.x;
        Bs[0][lcol + 1][lrow] = kb.y;
        Bs[0][lcol + 2][lrow] = kb.z;
        Bs[0][lcol + 3][lrow] = kb.w;
    }
    __syncthreads();

    int cur = 0;
    for (int ks = 0; ks < HDIM; ks += 8) {
        const int nxt = ks + 8;
        const bool more = nxt < HDIM;
        float4 a2, k2;
        if (more) {
            a2 = *(const float4*)(Q + (size_t)(t0 + lrow) * HDIM + nxt + lcol);
            k2 = *(const float4*)(K + (size_t)(s0 + lrow) * HDIM + nxt + lcol);
        }

        GEMM_INNER(As2[cur], Bs[cur], tr, tc)

        if (more) {
            const int nb = cur ^ 1;
            As2[nb][lcol + 0][lrow] = pack_dup_f32(a2.x);
            As2[nb][lcol + 1][lrow] = pack_dup_f32(a2.y);
            As2[nb][lcol + 2][lrow] = pack_dup_f32(a2.z);
            As2[nb][lcol + 3][lrow] = pack_dup_f32(a2.w);
            Bs[nb][lcol + 0][lrow] = k2.x;
            Bs[nb][lcol + 1][lrow] = k2.y;
            Bs[nb][lcol + 2][lrow] = k2.z;
            Bs[nb][lcol + 3][lrow] = k2.w;
            __syncthreads();
            cur = nb;
        }
    }

    const float SCALE = 11.313708498984761f;  // sqrt(128)
    float acc[8][8];
#pragma unroll
    for (int i = 0; i < 8; i++)
#pragma unroll
        for (int j = 0; j < 4; j++)
            unpack_f32x2(acc2[i][j], acc[i][j * 2], acc[i][j * 2 + 1]);

    if (s0 < t0) {
#pragma unroll
        for (int i = 0; i < 8; i++) {
            const int t = t0 + tr * 8 + i;
#pragma unroll
            for (int j = 0; j < 8; j += 4) {
                float4 o = make_float4(acc[i][j] * SCALE, acc[i][j + 1] * SCALE,
                                       acc[i][j + 2] * SCALE, acc[i][j + 3] * SCALE);
                *(float4*)(S + (size_t)t * SEQ + s0 + tc * 8 + j) = o;
            }
        }
    } else {
#pragma unroll
        for (int i = 0; i < 8; i++) {
            const int t = t0 + tr * 8 + i;
#pragma unroll
            for (int j = 0; j < 8; j += 4) {
                const int s = s0 + tc * 8 + j;
                float4 o;
                o.x = (s + 0 <= t) ? acc[i][j + 0] * SCALE : NEG_INF;
                o.y = (s + 1 <= t) ? acc[i][j + 1] * SCALE : NEG_INF;
                o.z = (s + 2 <= t) ? acc[i][j + 2] * SCALE : NEG_INF;
                o.w = (s + 3 <= t) ? acc[i][j + 3] * SCALE : NEG_INF;
                *(float4*)(S + (size_t)t * SEQ + s) = o;
            }
        }
    }
}

// =============================================================================
// Kernel C1: stats partials. For s-chunk sc and t-chunk tcb (tcb >= sc):
//   pm = max_{t in chunk, t>=s} S[t,s],  pl = sum exp(S-pm).
// grid = (8 s-chunks, 8 t-chunks, B), 256 threads (one per column s).
// =============================================================================
__global__ void __launch_bounds__(256) stats_part() {
    const int sc  = blockIdx.x;
    const int tcb = blockIdx.y;
    if (tcb < sc) return;                 // whole chunk above diagonal
    const int b  = blockIdx.z;
    const int s  = sc * 256 + threadIdx.x;
    const int tb = tcb * 256;
    const float* S = g_S + (size_t)b * SEQ * SEQ;

    float m = NEG_INF;
    float l = 0.f;

    for (int t = tb; t < tb + 256; t += 4) {
        float x0 = (t + 0 >= s) ? S[(size_t)(t + 0) * SEQ + s] : NEG_INF;
        float x1 = (t + 1 >= s) ? S[(size_t)(t + 1) * SEQ + s] : NEG_INF;
        float x2 = (t + 2 >= s) ? S[(size_t)(t + 2) * SEQ + s] : NEG_INF;
        float x3 = (t + 3 >= s) ? S[(size_t)(t + 3) * SEQ + s] : NEG_INF;
        float mx = fmaxf(fmaxf(x0, x1), fmaxf(x2, x3));
        if (mx > m) {
            l *= __expf(m - mx);   // m == -inf -> factor 0 (l already 0)
            m = mx;
        }
        if (m != NEG_INF) {
            l += __expf(x0 - m) + __expf(x1 - m) + __expf(x2 - m) + __expf(x3 - m);
        }
    }
    g_pm[(b * TCH + tcb) * SEQ + s] = m;
    g_pl[(b * TCH + tcb) * SEQ + s] = l;
}

// =============================================================================
// Kernel C2: combine partials ->  g_m[b,s], g_rl[b,s] = 1/l.
// grid = (SEQ/256, B)
// =============================================================================
__global__ void __launch_bounds__(256) stats_combine() {
    const int b = blockIdx.y;
    const int s = blockIdx.x * 256 + threadIdx.x;
    const int sc = s >> 8;

    float m = NEG_INF;
    for (int tcb = sc; tcb < TCH; tcb++)
        m = fmaxf(m, g_pm[(b * TCH + tcb) * SEQ + s]);
    float l = 0.f;
    for (int tcb = sc; tcb < TCH; tcb++) {
        float pm = g_pm[(b * TCH + tcb) * SEQ + s];
        float pl = g_pl[(b * TCH + tcb) * SEQ + s];
        if (pm != NEG_INF) l += pl * __expf(pm - m);
    }
    g_m[b * SEQ + s]  = m;
    g_rl[b * SEQ + s] = 1.f / l;
}

// =============================================================================
// Kernel D1: split-K PV partial.
//   g_Op[c][b,t,h] = sum_{s in chunk c, s<kend} exp(S[t,s]-m[s])*rl[s] * v[s,h]
// Per t-tile, kend = t0+128 (causal). Chunk K = 512 -> balance + occupancy.
// grid = (NCHUNK, T/128, B), 256 threads, 128x128x8 double-buffered tile.
// =============================================================================
__global__ void __launch_bounds__(256, 2) pv_partial() {
    const int c  = blockIdx.x;
    const int t0 = blockIdx.y * 128;
    const int b  = blockIdx.z;

    const int kend_t = t0 + 128;
    const int kbeg   = c * KCHUNK;
    if (kbeg >= kend_t) return;
    const int kend = (kbeg + KCHUNK < kend_t) ? (kbeg + KCHUNK) : kend_t;

    const float* S   = g_S  + (size_t)b * SEQ * SEQ;
    const float* V   = g_v  + (size_t)b * SEQ * HDIM;
    const float* mp  = g_m  + b * SEQ;
    const float* rlp = g_rl + b * SEQ;

    __shared__ u64   As2[2][8][128];
    __shared__ float Bs[2][8][128];

    const int tid  = threadIdx.x;
    const int tr   = tid / 16;
    const int tc   = tid % 16;
    const int arow = tid >> 1;
    const int acol = (tid & 1) * 4;
    const int b_r  = tid >> 5;
    const int b_c  = (tid & 31) * 4;

    u64 acc2[8][4] = {};

    {
        float4 a  = *(const float4*)(S + (size_t)(t0 + arow) * SEQ + kbeg + acol);
        float4 mm = *(const float4*)(mp + kbeg + acol);
        float4 rr = *(const float4*)(rlp + kbeg + acol);
        As2[0][acol + 0][arow] = pack_dup_f32(__expf(a.x - mm.x) * rr.x);  // -inf -> 0
        As2[0][acol + 1][arow] = pack_dup_f32(__expf(a.y - mm.y) * rr.y);
        As2[0][acol + 2][arow] = pack_dup_f32(__expf(a.z - mm.z) * rr.z);
        As2[0][acol + 3][arow] = pack_dup_f32(__expf(a.w - mm.w) * rr.w);
        float4 vb = *(const float4*)(V + (size_t)(kbeg + b_r) * HDIM + b_c);
        *(float4*)(&Bs[0][b_r][b_c]) = vb;
    }
    __syncthreads();

    int cur = 0;
    for (int ks = kbeg; ks < kend; ks += 8) {
        const int nxt = ks + 8;
        const bool more = nxt < kend;
        float4 a2, m2, r2, v2;
        if (more) {
            a2 = *(const float4*)(S + (size_t)(t0 + arow) * SEQ + nxt + acol);
            m2 = *(const float4*)(mp + nxt + acol);
            r2 = *(const float4*)(rlp + nxt + acol);
            v2 = *(const float4*)(V + (size_t)(nxt + b_r) * HDIM + b_c);
        }

        GEMM_INNER(As2[cur], Bs[cur], tr, tc)

        if (more) {
            const int nb = cur ^ 1;
            As2[nb][acol + 0][arow] = pack_dup_f32(__expf(a2.x - m2.x) * r2.x);
            As2[nb][acol + 1][arow] = pack_dup_f32(__expf(a2.y - m2.y) * r2.y);
            As2[nb][acol + 2][arow] = pack_dup_f32(__expf(a2.z - m2.z) * r2.z);
            As2[nb][acol + 3][arow] = pack_dup_f32(__expf(a2.w - m2.w) * r2.w);
            *(float4*)(&Bs[nb][b_r][b_c]) = v2;
            __syncthreads();
            cur = nb;
        }
    }

    float* Op = g_Op[c] + (size_t)b * SEQ * HDIM;
#pragma unroll
    for (int i = 0; i < 8; i++) {
        const int t = t0 + tr * 8 + i;
#pragma unroll
        for (int j = 0; j < 4; j += 2) {
            float4 o;
            unpack_f32x2(acc2[i][j],     o.x, o.y);
            unpack_f32x2(acc2[i][j + 1], o.z, o.w);
            *(float4*)(Op + (size_t)t * HDIM + tc * 8 + j * 2) = o;
        }
    }
}

// =============================================================================
// Kernel D2: reduce split-K partials. nc(t) = t/512 + 1 chunks contribute
// (chunk c ran for row t iff c*512 < floor(t/128)*128 + 128  <=>  c <= t/512).
// One thread per float4 of output.
// =============================================================================
__global__ void __launch_bounds__(256) pv_reduce(float* __restrict__ O) {
    const int idx4 = blockIdx.x * 256 + threadIdx.x;            // float4 index
    const int t    = (idx4 * 4 / HDIM) % SEQ;
    const int nc   = t / 512 + 1;

    float4 r = *(const float4*)(&g_Op[0][(size_t)idx4 * 4]);
    for (int c = 1; c < nc; c++) {
        float4 p = *(const float4*)(&g_Op[c][(size_t)idx4 * 4]);
        r.x += p.x; r.y += p.y; r.z += p.z; r.w += p.w;
    }
    *(float4*)(O + (size_t)idx4 * 4) = r;
}

// =============================================================================
extern "C" void kernel_launch(void* const* d_in, const int* in_sizes, int n_in,
                              void* d_out, int out_size) {
    const float* x  = (const float*)d_in[0];
    const float* Wk = (const float*)d_in[1];
    const float* Wq = (const float*)d_in[2];
    const float* Wv = (const float*)d_in[3];
    float* out = (float*)d_out;

    qkv_gemm<<<dim3((BATCH * SEQ) / 128, 1, 3), 256>>>(x, Wk, Wq, Wv);
    scores_kernel<<<dim3(SEQ / 128, SEQ / 128, BATCH), 256>>>();
    stats_part<<<dim3(SEQ / 256, TCH, BATCH), 256>>>();
    stats_combine<<<dim3(SEQ / 256, BATCH), 256>>>();
    pv_partial<<<dim3(NCHUNK, SEQ / 128, BATCH), 256>>>();
    pv_reduce<<<(BATCH * SEQ * HDIM / 4) / 256, 256>>>(out);
}

// round 8
// speedup vs baseline: 1.2455x; 1.2455x over previous
#include <cuda_runtime.h>
#include <cuda_fp16.h>
#include <cstdint>

#define BATCH 8
#define SEQ   2048
#define EDIM  1024
#define HDIM  128

#define NEG_INF (__int_as_float(0xff800000))

#define KCHUNK 512            // split-K chunk for PV
#define NCHUNK 4              // max chunks (2048/512)
#define TCH    8              // t-chunks for stats (2048/256)

typedef unsigned long long u64;

// ---------------- packed fp32x2 helpers (sm_100+ PTX) ------------------------
__device__ __forceinline__ u64 pack_dup_f32(float x) {
    u64 d;
    unsigned int xi = __float_as_uint(x);
    asm("mov.b64 %0, {%1, %2};" : "=l"(d) : "r"(xi), "r"(xi));
    return d;
}
__device__ __forceinline__ void fma_f32x2(u64& d, u64 a, u64 b) {
    asm("fma.rn.f32x2 %0, %1, %2, %3;" : "=l"(d) : "l"(a), "l"(b), "l"(d));
}
__device__ __forceinline__ void unpack_f32x2(u64 v, float& lo, float& hi) {
    unsigned int l32, h32;
    asm("mov.b64 {%0, %1}, %2;" : "=r"(l32), "=r"(h32) : "l"(v));
    lo = __uint_as_float(l32);
    hi = __uint_as_float(h32);
}

// ---------------- mma.sync / ldmatrix helpers (base PTX, no 'a' target) ------
__device__ __forceinline__ uint32_t smem_u32(const void* p) {
    uint32_t a;
    asm("{ .reg .u64 t; cvta.to.shared.u64 t, %1; cvt.u32.u64 %0, t; }" : "=r"(a) : "l"(p));
    return a;
}
__device__ __forceinline__ void ldsm_x4(uint32_t* r, uint32_t addr) {
    asm volatile("ldmatrix.sync.aligned.m8n8.x4.shared.b16 {%0,%1,%2,%3}, [%4];"
        : "=r"(r[0]), "=r"(r[1]), "=r"(r[2]), "=r"(r[3]) : "r"(addr));
}
__device__ __forceinline__ void mma16816(float* c, const uint32_t* a, uint32_t b0, uint32_t b1) {
    asm volatile("mma.sync.aligned.m16n8k16.row.col.f32.f16.f16.f32 "
        "{%0,%1,%2,%3}, {%4,%5,%6,%7}, {%8,%9}, {%0,%1,%2,%3};"
        : "+f"(c[0]), "+f"(c[1]), "+f"(c[2]), "+f"(c[3])
        : "r"(a[0]), "r"(a[1]), "r"(a[2]), "r"(a[3]), "r"(b0), "r"(b1));
}

// ---------------- scratch (device globals; no allocation allowed) ------------
__device__ float g_q[BATCH * SEQ * HDIM];
__device__ float g_k[BATCH * SEQ * HDIM];
__device__ float g_v[BATCH * SEQ * HDIM];
__device__ float g_S[(size_t)BATCH * SEQ * SEQ];          // 134 MB (upper triangle untouched)
__device__ float g_pm[BATCH * TCH * SEQ];                 // stats partials (max)
__device__ float g_pl[BATCH * TCH * SEQ];                 // stats partials (sum)
__device__ float g_m[BATCH * SEQ];
__device__ float g_rl[BATCH * SEQ];
__device__ float g_Op[NCHUNK][BATCH * SEQ * HDIM];        // PV split-K partials (33.5 MB)

// =============================================================================
// Kernel A (mma.sync HMMA): QKV projection via fp16 hi/lo split, fp32 accum.
// Y = X @ W for W in {Wk,Wq,Wv}. CTA tile 128x128, K=1024 in chunks of 32.
// 8 warps (4 m x 2 n), warp tile 32x64 (2 m-atoms x 8 n-atoms of m16n8k16).
// Per k16: Ahi*Bhi + Alo*Bhi + Ahi*Blo (lo*lo ~2^-22 dropped -> fp32 quality).
// Smem [128][40] f16: 80B rows -> ldmatrix conflict-free. grid = (128, 3).
// =============================================================================
#define QKC 32
__global__ void __launch_bounds__(256) qkv_mma(const float* __restrict__ X,
                                               const float* __restrict__ Wk,
                                               const float* __restrict__ Wq,
                                               const float* __restrict__ Wv) {
    __shared__ __half Ah[128][40], Al[128][40];   // A[m][k] hi/lo
    __shared__ __half Bh[128][40], Bl[128][40];   // B[n][k] hi/lo

    const float* W;
    float* Y;
    if (blockIdx.y == 0)      { W = Wk; Y = g_k; }
    else if (blockIdx.y == 1) { W = Wq; Y = g_q; }
    else                      { W = Wv; Y = g_v; }

    const int m0   = blockIdx.x * 128;
    const int tid  = threadIdx.x;
    const int wid  = tid / 32;
    const int lane = tid % 32;
    const int M0   = (wid >> 1) * 32;   // warp m offset in tile
    const int N0   = (wid & 1) * 64;    // warp n offset in tile

    // ldmatrix lane addressing components
    const int lq = lane >> 3;           // matrix index 0..3
    const int lr = lane & 7;            // row within 8x8

    float acc[2][8][4] = {};

    const int arow = tid >> 1;          // A load: row 0..127
    const int akh  = (tid & 1) * 16;    // k half
    const int bn   = tid & 127;         // B load: n
    const int bkq  = (tid >> 7) * 16;   // k half

    for (int k0 = 0; k0 < EDIM; k0 += QKC) {
        __syncthreads();   // previous chunk's ldmatrix reads complete

        // ---- A tile: 16 floats per thread -> hi/lo f16 ----
        {
            const float* xr = X + (size_t)(m0 + arow) * EDIM + k0 + akh;
            float4 v0 = *(const float4*)(xr + 0);
            float4 v1 = *(const float4*)(xr + 4);
            float4 v2 = *(const float4*)(xr + 8);
            float4 v3 = *(const float4*)(xr + 12);
            float f[16] = {v0.x, v0.y, v0.z, v0.w, v1.x, v1.y, v1.z, v1.w,
                           v2.x, v2.y, v2.z, v2.w, v3.x, v3.y, v3.z, v3.w};
            __half hs[16], ls[16];
#pragma unroll
            for (int i = 0; i < 16; i++) {
                hs[i] = __float2half_rn(f[i]);
                ls[i] = __float2half_rn(f[i] - __half2float(hs[i]));
            }
            *(uint4*)(&Ah[arow][akh + 0]) = ((uint4*)hs)[0];
            *(uint4*)(&Ah[arow][akh + 8]) = ((uint4*)hs)[1];
            *(uint4*)(&Al[arow][akh + 0]) = ((uint4*)ls)[0];
            *(uint4*)(&Al[arow][akh + 8]) = ((uint4*)ls)[1];
        }
        // ---- B tile: transpose W[k][n] -> B[n][k], hi/lo ----
        {
#pragma unroll
            for (int j = 0; j < 16; j++) {
                const float w = W[(size_t)(k0 + bkq + j) * HDIM + bn];
                const __half h = __float2half_rn(w);
                Bh[bn][bkq + j] = h;
                Bl[bn][bkq + j] = __float2half_rn(w - __half2float(h));
            }
        }
        __syncthreads();

        // ---- compute: 2 k16 steps ----
#pragma unroll
        for (int ks = 0; ks < QKC; ks += 16) {
            uint32_t a_hi[2][4], a_lo[2][4];
#pragma unroll
            for (int am = 0; am < 2; am++) {
                const int r = M0 + am * 16 + (lq & 1) * 8 + lr;
                const int c = ks + (lq >> 1) * 8;
                ldsm_x4(a_hi[am], smem_u32(&Ah[r][c]));
                ldsm_x4(a_lo[am], smem_u32(&Al[r][c]));
            }
#pragma unroll
            for (int pr = 0; pr < 4; pr++) {
                const int r = N0 + pr * 16 + (lq >> 1) * 8 + lr;
                const int c = ks + (lq & 1) * 8;
                uint32_t th[4], tl[4];
                ldsm_x4(th, smem_u32(&Bh[r][c]));
                ldsm_x4(tl, smem_u32(&Bl[r][c]));
#pragma unroll
                for (int am = 0; am < 2; am++) {
                    mma16816(acc[am][pr * 2 + 0], a_hi[am], th[0], th[1]);
                    mma16816(acc[am][pr * 2 + 1], a_hi[am], th[2], th[3]);
                    mma16816(acc[am][pr * 2 + 0], a_lo[am], th[0], th[1]);
                    mma16816(acc[am][pr * 2 + 1], a_lo[am], th[2], th[3]);
                    mma16816(acc[am][pr * 2 + 0], a_hi[am], tl[0], tl[1]);
                    mma16816(acc[am][pr * 2 + 1], a_hi[am], tl[2], tl[3]);
                }
            }
        }
    }

    // ---- epilogue: c0,c1 -> (row g, col 2*tig), c2,c3 -> row g+8 ----
    const int gr = lane >> 2;
    const int gc = (lane & 3) * 2;
#pragma unroll
    for (int am = 0; am < 2; am++) {
#pragma unroll
        for (int nb = 0; nb < 8; nb++) {
            const int mrow = m0 + M0 + am * 16 + gr;
            const int ncol = N0 + nb * 8 + gc;
            *(float2*)(Y + (size_t)mrow * HDIM + ncol) =
                make_float2(acc[am][nb][0], acc[am][nb][1]);
            *(float2*)(Y + (size_t)(mrow + 8) * HDIM + ncol) =
                make_float2(acc[am][nb][2], acc[am][nb][3]);
        }
    }
}

// =============================================================================
// FFMA2 inner product (unchanged from passing 715us version)
// =============================================================================
#define GEMM_INNER(AS2, BS, TRR, TCC)                                           \
    _Pragma("unroll")                                                           \
    for (int kk = 0; kk < 8; kk++) {                                            \
        u64 rb2[4];                                                             \
        _Pragma("unroll")                                                       \
        for (int j = 0; j < 4; j++)                                             \
            rb2[j] = *(const u64*)(&BS[kk][(TCC) * 8 + j * 2]);                 \
        _Pragma("unroll")                                                       \
        for (int i = 0; i < 8; i++) {                                           \
            const u64 ra2 = AS2[kk][(TRR) * 8 + i];                             \
            _Pragma("unroll")                                                   \
            for (int j = 0; j < 4; j++)                                         \
                fma_f32x2(acc2[i][j], ra2, rb2[j]);                             \
        }                                                                       \
    }

// =============================================================================
// Kernel B: S[b,t,s] = sqrt(H)*q.k for s<=t (diag tile -inf masked; above-diag
// tiles never written/read).  grid = (T/128, T/128, B)
// =============================================================================
__global__ void __launch_bounds__(256, 2) scores_kernel() {
    const int b  = blockIdx.z;
    const int t0 = blockIdx.y * 128;
    const int s0 = blockIdx.x * 128;
    if (s0 > t0) return;

    float* S = g_S + (size_t)b * SEQ * SEQ;
    const float* Q = g_q + (size_t)b * SEQ * HDIM;
    const float* K = g_k + (size_t)b * SEQ * HDIM;

    __shared__ u64   As2[2][8][128];
    __shared__ float Bs[2][8][128];

    const int tid  = threadIdx.x;
    const int tr   = tid / 16;
    const int tc   = tid % 16;
    const int lrow = tid >> 1;
    const int lcol = (tid & 1) * 4;

    u64 acc2[8][4] = {};

    {
        float4 a = *(const float4*)(Q + (size_t)(t0 + lrow) * HDIM + lcol);
        As2[0][lcol + 0][lrow] = pack_dup_f32(a.x);
        As2[0][lcol + 1][lrow] = pack_dup_f32(a.y);
        As2[0][lcol + 2][lrow] = pack_dup_f32(a.z);
        As2[0][lcol + 3][lrow] = pack_dup_f32(a.w);
        float4 kb = *(const float4*)(K + (size_t)(s0 + lrow) * HDIM + lcol);
        Bs[0][lcol + 0][lrow] = kb.x;
        Bs[0][lcol + 1][lrow] = kb.y;
        Bs[0][lcol + 2][lrow] = kb.z;
        Bs[0][lcol + 3][lrow] = kb.w;
    }
    __syncthreads();

    int cur = 0;
    for (int ks = 0; ks < HDIM; ks += 8) {
        const int nxt = ks + 8;
        const bool more = nxt < HDIM;
        float4 a2, k2;
        if (more) {
            a2 = *(const float4*)(Q + (size_t)(t0 + lrow) * HDIM + nxt + lcol);
            k2 = *(const float4*)(K + (size_t)(s0 + lrow) * HDIM + nxt + lcol);
        }

        GEMM_INNER(As2[cur], Bs[cur], tr, tc)

        if (more) {
            const int nb = cur ^ 1;
            As2[nb][lcol + 0][lrow] = pack_dup_f32(a2.x);
            As2[nb][lcol + 1][lrow] = pack_dup_f32(a2.y);
            As2[nb][lcol + 2][lrow] = pack_dup_f32(a2.z);
            As2[nb][lcol + 3][lrow] = pack_dup_f32(a2.w);
            Bs[nb][lcol + 0][lrow] = k2.x;
            Bs[nb][lcol + 1][lrow] = k2.y;
            Bs[nb][lcol + 2][lrow] = k2.z;
            Bs[nb][lcol + 3][lrow] = k2.w;
            __syncthreads();
            cur = nb;
        }
    }

    const float SCALE = 11.313708498984761f;  // sqrt(128)
    float acc[8][8];
#pragma unroll
    for (int i = 0; i < 8; i++)
#pragma unroll
        for (int j = 0; j < 4; j++)
            unpack_f32x2(acc2[i][j], acc[i][j * 2], acc[i][j * 2 + 1]);

    if (s0 < t0) {
#pragma unroll
        for (int i = 0; i < 8; i++) {
            const int t = t0 + tr * 8 + i;
#pragma unroll
            for (int j = 0; j < 8; j += 4) {
                float4 o = make_float4(acc[i][j] * SCALE, acc[i][j + 1] * SCALE,
                                       acc[i][j + 2] * SCALE, acc[i][j + 3] * SCALE);
                *(float4*)(S + (size_t)t * SEQ + s0 + tc * 8 + j) = o;
            }
        }
    } else {
#pragma unroll
        for (int i = 0; i < 8; i++) {
            const int t = t0 + tr * 8 + i;
#pragma unroll
            for (int j = 0; j < 8; j += 4) {
                const int s = s0 + tc * 8 + j;
                float4 o;
                o.x = (s + 0 <= t) ? acc[i][j + 0] * SCALE : NEG_INF;
                o.y = (s + 1 <= t) ? acc[i][j + 1] * SCALE : NEG_INF;
                o.z = (s + 2 <= t) ? acc[i][j + 2] * SCALE : NEG_INF;
                o.w = (s + 3 <= t) ? acc[i][j + 3] * SCALE : NEG_INF;
                *(float4*)(S + (size_t)t * SEQ + s) = o;
            }
        }
    }
}

// =============================================================================
// Kernel C1: stats partials (column softmax over t). grid = (8, 8, B)
// =============================================================================
__global__ void __launch_bounds__(256) stats_part() {
    const int sc  = blockIdx.x;
    const int tcb = blockIdx.y;
    if (tcb < sc) return;
    const int b  = blockIdx.z;
    const int s  = sc * 256 + threadIdx.x;
    const int tb = tcb * 256;
    const float* S = g_S + (size_t)b * SEQ * SEQ;

    float m = NEG_INF;
    float l = 0.f;

    for (int t = tb; t < tb + 256; t += 4) {
        float x0 = (t + 0 >= s) ? S[(size_t)(t + 0) * SEQ + s] : NEG_INF;
        float x1 = (t + 1 >= s) ? S[(size_t)(t + 1) * SEQ + s] : NEG_INF;
        float x2 = (t + 2 >= s) ? S[(size_t)(t + 2) * SEQ + s] : NEG_INF;
        float x3 = (t + 3 >= s) ? S[(size_t)(t + 3) * SEQ + s] : NEG_INF;
        float mx = fmaxf(fmaxf(x0, x1), fmaxf(x2, x3));
        if (mx > m) {
            l *= __expf(m - mx);
            m = mx;
        }
        if (m != NEG_INF) {
            l += __expf(x0 - m) + __expf(x1 - m) + __expf(x2 - m) + __expf(x3 - m);
        }
    }
    g_pm[(b * TCH + tcb) * SEQ + s] = m;
    g_pl[(b * TCH + tcb) * SEQ + s] = l;
}

// =============================================================================
// Kernel C2: combine stats partials. grid = (SEQ/256, B)
// =============================================================================
__global__ void __launch_bounds__(256) stats_combine() {
    const int b = blockIdx.y;
    const int s = blockIdx.x * 256 + threadIdx.x;
    const int sc = s >> 8;

    float m = NEG_INF;
    for (int tcb = sc; tcb < TCH; tcb++)
        m = fmaxf(m, g_pm[(b * TCH + tcb) * SEQ + s]);
    float l = 0.f;
    for (int tcb = sc; tcb < TCH; tcb++) {
        float pm = g_pm[(b * TCH + tcb) * SEQ + s];
        float pl = g_pl[(b * TCH + tcb) * SEQ + s];
        if (pm != NEG_INF) l += pl * __expf(pm - m);
    }
    g_m[b * SEQ + s]  = m;
    g_rl[b * SEQ + s] = 1.f / l;
}

// =============================================================================
// Kernel D1: split-K PV partial. grid = (NCHUNK, T/128, B)
// =============================================================================
__global__ void __launch_bounds__(256, 2) pv_partial() {
    const int c  = blockIdx.x;
    const int t0 = blockIdx.y * 128;
    const int b  = blockIdx.z;

    const int kend_t = t0 + 128;
    const int kbeg   = c * KCHUNK;
    if (kbeg >= kend_t) return;
    const int kend = (kbeg + KCHUNK < kend_t) ? (kbeg + KCHUNK) : kend_t;

    const float* S   = g_S  + (size_t)b * SEQ * SEQ;
    const float* V   = g_v  + (size_t)b * SEQ * HDIM;
    const float* mp  = g_m  + b * SEQ;
    const float* rlp = g_rl + b * SEQ;

    __shared__ u64   As2[2][8][128];
    __shared__ float Bs[2][8][128];

    const int tid  = threadIdx.x;
    const int tr   = tid / 16;
    const int tc   = tid % 16;
    const int arow = tid >> 1;
    const int acol = (tid & 1) * 4;
    const int b_r  = tid >> 5;
    const int b_c  = (tid & 31) * 4;

    u64 acc2[8][4] = {};

    {
        float4 a  = *(const float4*)(S + (size_t)(t0 + arow) * SEQ + kbeg + acol);
        float4 mm = *(const float4*)(mp + kbeg + acol);
        float4 rr = *(const float4*)(rlp + kbeg + acol);
        As2[0][acol + 0][arow] = pack_dup_f32(__expf(a.x - mm.x) * rr.x);
        As2[0][acol + 1][arow] = pack_dup_f32(__expf(a.y - mm.y) * rr.y);
        As2[0][acol + 2][arow] = pack_dup_f32(__expf(a.z - mm.z) * rr.z);
        As2[0][acol + 3][arow] = pack_dup_f32(__expf(a.w - mm.w) * rr.w);
        float4 vb = *(const float4*)(V + (size_t)(kbeg + b_r) * HDIM + b_c);
        *(float4*)(&Bs[0][b_r][b_c]) = vb;
    }
    __syncthreads();

    int cur = 0;
    for (int ks = kbeg; ks < kend; ks += 8) {
        const int nxt = ks + 8;
        const bool more = nxt < kend;
        float4 a2, m2, r2, v2;
        if (more) {
            a2 = *(const float4*)(S + (size_t)(t0 + arow) * SEQ + nxt + acol);
            m2 = *(const float4*)(mp + nxt + acol);
            r2 = *(const float4*)(rlp + nxt + acol);
            v2 = *(const float4*)(V + (size_t)(nxt + b_r) * HDIM + b_c);
        }

        GEMM_INNER(As2[cur], Bs[cur], tr, tc)

        if (more) {
            const int nb = cur ^ 1;
            As2[nb][acol + 0][arow] = pack_dup_f32(__expf(a2.x - m2.x) * r2.x);
            As2[nb][acol + 1][arow] = pack_dup_f32(__expf(a2.y - m2.y) * r2.y);
            As2[nb][acol + 2][arow] = pack_dup_f32(__expf(a2.z - m2.z) * r2.z);
            As2[nb][acol + 3][arow] = pack_dup_f32(__expf(a2.w - m2.w) * r2.w);
            *(float4*)(&Bs[nb][b_r][b_c]) = v2;
            __syncthreads();
            cur = nb;
        }
    }

    float* Op = g_Op[c] + (size_t)b * SEQ * HDIM;
#pragma unroll
    for (int i = 0; i < 8; i++) {
        const int t = t0 + tr * 8 + i;
#pragma unroll
        for (int j = 0; j < 4; j += 2) {
            float4 o;
            unpack_f32x2(acc2[i][j],     o.x, o.y);
            unpack_f32x2(acc2[i][j + 1], o.z, o.w);
            *(float4*)(Op + (size_t)t * HDIM + tc * 8 + j * 2) = o;
        }
    }
}

// =============================================================================
// Kernel D2: reduce split-K partials. nc(t) = t/512 + 1.
// =============================================================================
__global__ void __launch_bounds__(256) pv_reduce(float* __restrict__ O) {
    const int idx4 = blockIdx.x * 256 + threadIdx.x;
    const int t    = (idx4 * 4 / HDIM) % SEQ;
    const int nc   = t / 512 + 1;

    float4 r = *(const float4*)(&g_Op[0][(size_t)idx4 * 4]);
    for (int c = 1; c < nc; c++) {
        float4 p = *(const float4*)(&g_Op[c][(size_t)idx4 * 4]);
        r.x += p.x; r.y += p.y; r.z += p.z; r.w += p.w;
    }
    *(float4*)(O + (size_t)idx4 * 4) = r;
}

// =============================================================================
extern "C" void kernel_launch(void* const* d_in, const int* in_sizes, int n_in,
                              void* d_out, int out_size) {
    const float* x  = (const float*)d_in[0];
    const float* Wk = (const float*)d_in[1];
    const float* Wq = (const float*)d_in[2];
    const float* Wv = (const float*)d_in[3];
    float* out = (float*)d_out;

    qkv_mma<<<dim3((BATCH * SEQ) / 128, 3), 256>>>(x, Wk, Wq, Wv);
    scores_kernel<<<dim3(SEQ / 128, SEQ / 128, BATCH), 256>>>();
    stats_part<<<dim3(SEQ / 256, TCH, BATCH), 256>>>();
    stats_combine<<<dim3(SEQ / 256, BATCH), 256>>>();
    pv_partial<<<dim3(NCHUNK, SEQ / 128, BATCH), 256>>>();
    pv_reduce<<<(BATCH * SEQ * HDIM / 4) / 256, 256>>>(out);
}

// round 16
// speedup vs baseline: 1.6088x; 1.2917x over previous
#include <cuda_runtime.h>
#include <cuda_fp16.h>
#include <cstdint>

#define BATCH 8
#define SEQ   2048
#define EDIM  1024
#define HDIM  128

#define NEG_INF (__int_as_float(0xff800000))

#define KCHUNK 512            // split-K chunk for PV
#define NCHUNK 4              // max chunks (2048/512)
#define TCH    8              // t-chunks for stats (2048/256)

// ---------------- mma.sync / ldmatrix helpers (base PTX, no 'a' target) ------
__device__ __forceinline__ uint32_t smem_u32(const void* p) {
    uint32_t a;
    asm("{ .reg .u64 t; cvta.to.shared.u64 t, %1; cvt.u32.u64 %0, t; }" : "=r"(a) : "l"(p));
    return a;
}
__device__ __forceinline__ void ldsm_x4(uint32_t* r, uint32_t addr) {
    asm volatile("ldmatrix.sync.aligned.m8n8.x4.shared.b16 {%0,%1,%2,%3}, [%4];"
        : "=r"(r[0]), "=r"(r[1]), "=r"(r[2]), "=r"(r[3]) : "r"(addr));
}
__device__ __forceinline__ void ldsm_x4_t(uint32_t* r, uint32_t addr) {
    asm volatile("ldmatrix.sync.aligned.m8n8.x4.trans.shared.b16 {%0,%1,%2,%3}, [%4];"
        : "=r"(r[0]), "=r"(r[1]), "=r"(r[2]), "=r"(r[3]) : "r"(addr));
}
__device__ __forceinline__ void mma16816(float* c, const uint32_t* a, uint32_t b0, uint32_t b1) {
    asm volatile("mma.sync.aligned.m16n8k16.row.col.f32.f16.f16.f32 "
        "{%0,%1,%2,%3}, {%4,%5,%6,%7}, {%8,%9}, {%0,%1,%2,%3};"
        : "+f"(c[0]), "+f"(c[1]), "+f"(c[2]), "+f"(c[3])
        : "r"(a[0]), "r"(a[1]), "r"(a[2]), "r"(a[3]), "r"(b0), "r"(b1));
}

// ---------------- scratch (device globals; no allocation allowed) ------------
__device__ __half g_qh[BATCH * SEQ * HDIM];               // q hi (f16 split)
__device__ __half g_ql[BATCH * SEQ * HDIM];               // q lo
__device__ __half g_kh[BATCH * SEQ * HDIM];               // k hi
__device__ __half g_kl[BATCH * SEQ * HDIM];               // k lo
__device__ float g_v[BATCH * SEQ * HDIM];
__device__ float g_S[(size_t)BATCH * SEQ * SEQ];          // 134 MB (upper triangle untouched)
__device__ float g_pm[BATCH * TCH * SEQ];                 // stats partials (max)
__device__ float g_pl[BATCH * TCH * SEQ];                 // stats partials (sum)
__device__ float g_m[BATCH * SEQ];
__device__ float g_rl[BATCH * SEQ];
__device__ float g_Op[NCHUNK][BATCH * SEQ * HDIM];        // PV split-K partials (33.5 MB)

__device__ __forceinline__ void store_hl(__half* H, __half* L, size_t off, float a, float b) {
    __half ha = __float2half_rn(a), hb = __float2half_rn(b);
    __half la = __float2half_rn(a - __half2float(ha));
    __half lb = __float2half_rn(b - __half2float(hb));
    *(__half2*)(H + off) = __halves2half2(ha, hb);
    *(__half2*)(L + off) = __halves2half2(la, lb);
}

// =============================================================================
// Kernel A (mma.sync HMMA): QKV projection via fp16 hi/lo split, fp32 accum.
// Y = X @ W for W in {Wk,Wq,Wv}. CTA tile 128x128, K=1024 in chunks of 32.
// 8 warps (4 m x 2 n), warp tile 32x64 (2 m-atoms x 8 n-atoms of m16n8k16).
// Per k16: Ahi*Bhi + Alo*Bhi + Ahi*Blo (lo*lo ~2^-22 dropped -> fp32 quality).
// Q/K outputs stored as pre-split f16 hi/lo (consumed by scores_mma); V fp32.
// Fragment mapping (VALIDATED in the 574us R8 pass, do not change):
//   A matrix i: m-off (i&1)*8, k-off (i>>1)*8
//   B matrix i: n-off (i>>1)*8, k-off (i&1)*8
// Smem [128][40] f16: 80B rows -> ldmatrix conflict-free. grid = (128, 3).
// =============================================================================
#define QKC 32
__global__ void __launch_bounds__(256) qkv_mma(const float* __restrict__ X,
                                               const float* __restrict__ Wk,
                                               const float* __restrict__ Wq,
                                               const float* __restrict__ Wv) {
    __shared__ __half Ah[128][40], Al[128][40];   // A[m][k] hi/lo
    __shared__ __half Bh[128][40], Bl[128][40];   // B[n][k] hi/lo

    const float* W;
    if (blockIdx.y == 0)      W = Wk;
    else if (blockIdx.y == 1) W = Wq;
    else                      W = Wv;

    const int m0   = blockIdx.x * 128;
    const int tid  = threadIdx.x;
    const int wid  = tid / 32;
    const int lane = tid % 32;
    const int M0   = (wid >> 1) * 32;
    const int N0   = (wid & 1) * 64;
    const int lq   = lane >> 3;
    const int lr   = lane & 7;

    float acc[2][8][4] = {};

    const int arow = tid >> 1;
    const int akh  = (tid & 1) * 16;
    const int bn   = tid & 127;
    const int bkq  = (tid >> 7) * 16;

    for (int k0 = 0; k0 < EDIM; k0 += QKC) {
        __syncthreads();

        {
            const float* xr = X + (size_t)(m0 + arow) * EDIM + k0 + akh;
            float4 v0 = *(const float4*)(xr + 0);
            float4 v1 = *(const float4*)(xr + 4);
            float4 v2 = *(const float4*)(xr + 8);
            float4 v3 = *(const float4*)(xr + 12);
            float f[16] = {v0.x, v0.y, v0.z, v0.w, v1.x, v1.y, v1.z, v1.w,
                           v2.x, v2.y, v2.z, v2.w, v3.x, v3.y, v3.z, v3.w};
            __half hs[16], ls[16];
#pragma unroll
            for (int i = 0; i < 16; i++) {
                hs[i] = __float2half_rn(f[i]);
                ls[i] = __float2half_rn(f[i] - __half2float(hs[i]));
            }
            *(uint4*)(&Ah[arow][akh + 0]) = ((uint4*)hs)[0];
            *(uint4*)(&Ah[arow][akh + 8]) = ((uint4*)hs)[1];
            *(uint4*)(&Al[arow][akh + 0]) = ((uint4*)ls)[0];
            *(uint4*)(&Al[arow][akh + 8]) = ((uint4*)ls)[1];
        }
        {
#pragma unroll
            for (int j = 0; j < 16; j++) {
                const float w = W[(size_t)(k0 + bkq + j) * HDIM + bn];
                const __half h = __float2half_rn(w);
                Bh[bn][bkq + j] = h;
                Bl[bn][bkq + j] = __float2half_rn(w - __half2float(h));
            }
        }
        __syncthreads();

#pragma unroll
        for (int ks = 0; ks < QKC; ks += 16) {
            uint32_t a_hi[2][4], a_lo[2][4];
#pragma unroll
            for (int am = 0; am < 2; am++) {
                const int r = M0 + am * 16 + (lq & 1) * 8 + lr;
                const int c = ks + (lq >> 1) * 8;
                ldsm_x4(a_hi[am], smem_u32(&Ah[r][c]));
                ldsm_x4(a_lo[am], smem_u32(&Al[r][c]));
            }
#pragma unroll
            for (int pr = 0; pr < 4; pr++) {
                const int r = N0 + pr * 16 + (lq >> 1) * 8 + lr;
                const int c = ks + (lq & 1) * 8;
                uint32_t th[4], tl[4];
                ldsm_x4(th, smem_u32(&Bh[r][c]));
                ldsm_x4(tl, smem_u32(&Bl[r][c]));
#pragma unroll
                for (int am = 0; am < 2; am++) {
                    mma16816(acc[am][pr * 2 + 0], a_hi[am], th[0], th[1]);
                    mma16816(acc[am][pr * 2 + 1], a_hi[am], th[2], th[3]);
                    mma16816(acc[am][pr * 2 + 0], a_lo[am], th[0], th[1]);
                    mma16816(acc[am][pr * 2 + 1], a_lo[am], th[2], th[3]);
                    mma16816(acc[am][pr * 2 + 0], a_hi[am], tl[0], tl[1]);
                    mma16816(acc[am][pr * 2 + 1], a_hi[am], tl[2], tl[3]);
                }
            }
        }
    }

    const int gr = lane >> 2;
    const int gc = (lane & 3) * 2;
    if (blockIdx.y == 2) {
        // V: fp32
#pragma unroll
        for (int am = 0; am < 2; am++)
#pragma unroll
            for (int nb = 0; nb < 8; nb++) {
                const int mrow = m0 + M0 + am * 16 + gr;
                const int ncol = N0 + nb * 8 + gc;
                *(float2*)(g_v + (size_t)mrow * HDIM + ncol) =
                    make_float2(acc[am][nb][0], acc[am][nb][1]);
                *(float2*)(g_v + (size_t)(mrow + 8) * HDIM + ncol) =
                    make_float2(acc[am][nb][2], acc[am][nb][3]);
            }
    } else {
        // Q/K: pre-split f16 hi/lo for scores_mma
        __half* H = (blockIdx.y == 0) ? g_kh : g_qh;
        __half* L = (blockIdx.y == 0) ? g_kl : g_ql;
#pragma unroll
        for (int am = 0; am < 2; am++)
#pragma unroll
            for (int nb = 0; nb < 8; nb++) {
                const int mrow = m0 + M0 + am * 16 + gr;
                const int ncol = N0 + nb * 8 + gc;
                store_hl(H, L, (size_t)mrow * HDIM + ncol, acc[am][nb][0], acc[am][nb][1]);
                store_hl(H, L, (size_t)(mrow + 8) * HDIM + ncol, acc[am][nb][2], acc[am][nb][3]);
            }
    }
}

// =============================================================================
// Kernel B (mma.sync HMMA): S = sqrt(H) * Q.K^T, causal. Q/K come pre-split
// f16 hi/lo from qkv_mma. CTA tile 128x128, K=128 in 4 chunks of 32, same
// warp layout and VALIDATED fragment mapping as qkv_mma. Diagonal tiles mask
// s>t with -inf; above-diagonal tiles skipped. grid = (16, 16, B).
// =============================================================================
__global__ void __launch_bounds__(256) scores_mma() {
    const int b  = blockIdx.z;
    const int t0 = blockIdx.y * 128;
    const int s0 = blockIdx.x * 128;
    if (s0 > t0) return;

    __shared__ __half Ah[128][40], Al[128][40];   // Q rows
    __shared__ __half Bh[128][40], Bl[128][40];   // K rows

    const __half* Qh = g_qh + (size_t)b * SEQ * HDIM;
    const __half* Ql = g_ql + (size_t)b * SEQ * HDIM;
    const __half* Kh = g_kh + (size_t)b * SEQ * HDIM;
    const __half* Kl = g_kl + (size_t)b * SEQ * HDIM;
    float* S = g_S + (size_t)b * SEQ * SEQ;

    const int tid  = threadIdx.x;
    const int wid  = tid / 32;
    const int lane = tid % 32;
    const int M0   = (wid >> 1) * 32;
    const int N0   = (wid & 1) * 64;
    const int lq   = lane >> 3;
    const int lr   = lane & 7;

    float acc[2][8][4] = {};

    const int arow = tid >> 1;
    const int akh  = (tid & 1) * 16;
    const int bn   = tid & 127;
    const int bkq  = (tid >> 7) * 16;

    for (int k0 = 0; k0 < HDIM; k0 += 32) {
        __syncthreads();
        *(uint4*)(&Ah[arow][akh + 0]) = *(const uint4*)(Qh + (size_t)(t0 + arow) * HDIM + k0 + akh);
        *(uint4*)(&Ah[arow][akh + 8]) = *(const uint4*)(Qh + (size_t)(t0 + arow) * HDIM + k0 + akh + 8);
        *(uint4*)(&Al[arow][akh + 0]) = *(const uint4*)(Ql + (size_t)(t0 + arow) * HDIM + k0 + akh);
        *(uint4*)(&Al[arow][akh + 8]) = *(const uint4*)(Ql + (size_t)(t0 + arow) * HDIM + k0 + akh + 8);
        *(uint4*)(&Bh[bn][bkq + 0])   = *(const uint4*)(Kh + (size_t)(s0 + bn) * HDIM + k0 + bkq);
        *(uint4*)(&Bh[bn][bkq + 8])   = *(const uint4*)(Kh + (size_t)(s0 + bn) * HDIM + k0 + bkq + 8);
        *(uint4*)(&Bl[bn][bkq + 0])   = *(const uint4*)(Kl + (size_t)(s0 + bn) * HDIM + k0 + bkq);
        *(uint4*)(&Bl[bn][bkq + 8])   = *(const uint4*)(Kl + (size_t)(s0 + bn) * HDIM + k0 + bkq + 8);
        __syncthreads();

#pragma unroll
        for (int ks = 0; ks < 32; ks += 16) {
            uint32_t a_hi[2][4], a_lo[2][4];
#pragma unroll
            for (int am = 0; am < 2; am++) {
                const int r = M0 + am * 16 + (lq & 1) * 8 + lr;
                const int c = ks + (lq >> 1) * 8;
                ldsm_x4(a_hi[am], smem_u32(&Ah[r][c]));
                ldsm_x4(a_lo[am], smem_u32(&Al[r][c]));
            }
#pragma unroll
            for (int pr = 0; pr < 4; pr++) {
                const int r = N0 + pr * 16 + (lq >> 1) * 8 + lr;
                const int c = ks + (lq & 1) * 8;
                uint32_t th[4], tl[4];
                ldsm_x4(th, smem_u32(&Bh[r][c]));
                ldsm_x4(tl, smem_u32(&Bl[r][c]));
#pragma unroll
                for (int am = 0; am < 2; am++) {
                    mma16816(acc[am][pr * 2 + 0], a_hi[am], th[0], th[1]);
                    mma16816(acc[am][pr * 2 + 1], a_hi[am], th[2], th[3]);
                    mma16816(acc[am][pr * 2 + 0], a_lo[am], th[0], th[1]);
                    mma16816(acc[am][pr * 2 + 1], a_lo[am], th[2], th[3]);
                    mma16816(acc[am][pr * 2 + 0], a_hi[am], tl[0], tl[1]);
                    mma16816(acc[am][pr * 2 + 1], a_hi[am], tl[2], tl[3]);
                }
            }
        }
    }

    const float SCALE = 11.313708498984761f;  // sqrt(128)
    const int gr = lane >> 2;
    const int gc = (lane & 3) * 2;
    const bool diag = (s0 == t0);
#pragma unroll
    for (int am = 0; am < 2; am++)
#pragma unroll
        for (int nb = 0; nb < 8; nb++) {
            const int t = t0 + M0 + am * 16 + gr;
            const int s = s0 + N0 + nb * 8 + gc;
            float2 v01 = make_float2(acc[am][nb][0] * SCALE, acc[am][nb][1] * SCALE);
            float2 v23 = make_float2(acc[am][nb][2] * SCALE, acc[am][nb][3] * SCALE);
            if (diag) {
                if (s > t)         v01.x = NEG_INF;
                if (s + 1 > t)     v01.y = NEG_INF;
                if (s > t + 8)     v23.x = NEG_INF;
                if (s + 1 > t + 8) v23.y = NEG_INF;
            }
            *(float2*)(S + (size_t)t * SEQ + s) = v01;
            *(float2*)(S + (size_t)(t + 8) * SEQ + s) = v23;
        }
}

// =============================================================================
// Kernel C1: stats partials (column softmax over t). grid = (8, 8, B)
// =============================================================================
__global__ void __launch_bounds__(256) stats_part() {
    const int sc  = blockIdx.x;
    const int tcb = blockIdx.y;
    if (tcb < sc) return;
    const int b  = blockIdx.z;
    const int s  = sc * 256 + threadIdx.x;
    const int tb = tcb * 256;
    const float* S = g_S + (size_t)b * SEQ * SEQ;

    float m = NEG_INF;
    float l = 0.f;

    for (int t = tb; t < tb + 256; t += 4) {
        float x0 = (t + 0 >= s) ? S[(size_t)(t + 0) * SEQ + s] : NEG_INF;
        float x1 = (t + 1 >= s) ? S[(size_t)(t + 1) * SEQ + s] : NEG_INF;
        float x2 = (t + 2 >= s) ? S[(size_t)(t + 2) * SEQ + s] : NEG_INF;
        float x3 = (t + 3 >= s) ? S[(size_t)(t + 3) * SEQ + s] : NEG_INF;
        float mx = fmaxf(fmaxf(x0, x1), fmaxf(x2, x3));
        if (mx > m) {
            l *= __expf(m - mx);
            m = mx;
        }
        if (m != NEG_INF) {
            l += __expf(x0 - m) + __expf(x1 - m) + __expf(x2 - m) + __expf(x3 - m);
        }
    }
    g_pm[(b * TCH + tcb) * SEQ + s] = m;
    g_pl[(b * TCH + tcb) * SEQ + s] = l;
}

// =============================================================================
// Kernel C2: combine stats partials. grid = (SEQ/256, B)
// =============================================================================
__global__ void __launch_bounds__(256) stats_combine() {
    const int b = blockIdx.y;
    const int s = blockIdx.x * 256 + threadIdx.x;
    const int sc = s >> 8;

    float m = NEG_INF;
    for (int tcb = sc; tcb < TCH; tcb++)
        m = fmaxf(m, g_pm[(b * TCH + tcb) * SEQ + s]);
    float l = 0.f;
    for (int tcb = sc; tcb < TCH; tcb++) {
        float pm = g_pm[(b * TCH + tcb) * SEQ + s];
        float pl = g_pl[(b * TCH + tcb) * SEQ + s];
        if (pm != NEG_INF) l += pl * __expf(pm - m);
    }
    g_m[b * SEQ + s]  = m;
    g_rl[b * SEQ + s] = 1.f / l;
}

// =============================================================================
// Kernel D1 (mma.sync HMMA): split-K PV partial.
//   g_Op[c][b,t,h] = sum_{s in chunk, s<t0+128} P[t,s] * V[s,h],
//   P = exp(S-m[s])*rl[s], computed in-kernel and hi/lo split (3-pass HMMA).
// A = P: smem [128][40] (validated non-trans A layout).
// B = V: smem [32][136] row-major [s][h]; fragments via ldmatrix.x4.trans.
// Trans addressing derived from the VALIDATED non-trans mapping
// (B matrix i: n-off (i>>1)*8, k-off (i&1)*8): stored [k][n] block must have
// k-rows ks+(i&1)*8+lr and n-cols N0+pr*16+(i>>1)*8 — transpose gives the
// identical fragment content (re-derived from the documented m16n8k16 B
// register layout; triple-checked, frozen).
// grid = (NCHUNK, T/128, B), 256 threads.
// =============================================================================
__global__ void __launch_bounds__(256) pv_mma() {
    const int c  = blockIdx.x;
    const int t0 = blockIdx.y * 128;
    const int b  = blockIdx.z;

    const int kend_t = t0 + 128;
    const int kbeg   = c * KCHUNK;
    if (kbeg >= kend_t) return;
    const int kend = (kbeg + KCHUNK < kend_t) ? (kbeg + KCHUNK) : kend_t;

    __shared__ __half Ph[128][40], Pl[128][40];   // P[t][s_local] hi/lo
    __shared__ __half Vh[32][136],  Vl[32][136];  // V[s_local][h] hi/lo

    const float* S   = g_S  + (size_t)b * SEQ * SEQ;
    const float* V   = g_v  + (size_t)b * SEQ * HDIM;
    const float* mp  = g_m  + b * SEQ;
    const float* rlp = g_rl + b * SEQ;

    const int tid  = threadIdx.x;
    const int wid  = tid / 32;
    const int lane = tid % 32;
    const int M0   = (wid >> 1) * 32;   // t offset
    const int N0   = (wid & 1) * 64;    // h offset
    const int lq   = lane >> 3;
    const int lr   = lane & 7;

    float acc[2][8][4] = {};

    const int arow = tid >> 1;          // P row (t local)
    const int acol = (tid & 1) * 16;    // P col (s local half)
    const int vrow = tid >> 3;          // V row (s local)
    const int vh0  = (tid & 7) * 16;    // V col (h)

    for (int k0 = kbeg; k0 < kend; k0 += 32) {
        __syncthreads();

        // ---- P tile: exp(S-m)*rl, hi/lo split ----
        {
            const float* sr = S + (size_t)(t0 + arow) * SEQ + k0 + acol;
            float p[16];
#pragma unroll
            for (int g = 0; g < 4; g++) {
                float4 sv = *(const float4*)(sr + g * 4);
                float4 mv = *(const float4*)(mp + k0 + acol + g * 4);
                float4 rv = *(const float4*)(rlp + k0 + acol + g * 4);
                p[g * 4 + 0] = __expf(sv.x - mv.x) * rv.x;   // -inf -> 0
                p[g * 4 + 1] = __expf(sv.y - mv.y) * rv.y;
                p[g * 4 + 2] = __expf(sv.z - mv.z) * rv.z;
                p[g * 4 + 3] = __expf(sv.w - mv.w) * rv.w;
            }
            __half hs[16], ls[16];
#pragma unroll
            for (int i = 0; i < 16; i++) {
                hs[i] = __float2half_rn(p[i]);
                ls[i] = __float2half_rn(p[i] - __half2float(hs[i]));
            }
            *(uint4*)(&Ph[arow][acol + 0]) = ((uint4*)hs)[0];
            *(uint4*)(&Ph[arow][acol + 8]) = ((uint4*)hs)[1];
            *(uint4*)(&Pl[arow][acol + 0]) = ((uint4*)ls)[0];
            *(uint4*)(&Pl[arow][acol + 8]) = ((uint4*)ls)[1];
        }
        // ---- V tile: [s][h] row-major, hi/lo split ----
        {
            const float* vr = V + (size_t)(k0 + vrow) * HDIM + vh0;
            float4 v0 = *(const float4*)(vr + 0);
            float4 v1 = *(const float4*)(vr + 4);
            float4 v2 = *(const float4*)(vr + 8);
            float4 v3 = *(const float4*)(vr + 12);
            float f[16] = {v0.x, v0.y, v0.z, v0.w, v1.x, v1.y, v1.z, v1.w,
                           v2.x, v2.y, v2.z, v2.w, v3.x, v3.y, v3.z, v3.w};
            __half hs[16], ls[16];
#pragma unroll
            for (int i = 0; i < 16; i++) {
                hs[i] = __float2half_rn(f[i]);
                ls[i] = __float2half_rn(f[i] - __half2float(hs[i]));
            }
            *(uint4*)(&Vh[vrow][vh0 + 0]) = ((uint4*)hs)[0];
            *(uint4*)(&Vh[vrow][vh0 + 8]) = ((uint4*)hs)[1];
            *(uint4*)(&Vl[vrow][vh0 + 0]) = ((uint4*)ls)[0];
            *(uint4*)(&Vl[vrow][vh0 + 8]) = ((uint4*)ls)[1];
        }
        __syncthreads();

#pragma unroll
        for (int ks = 0; ks < 32; ks += 16) {
            uint32_t a_hi[2][4], a_lo[2][4];
#pragma unroll
            for (int am = 0; am < 2; am++) {
                const int r = M0 + am * 16 + (lq & 1) * 8 + lr;
                const int cc = ks + (lq >> 1) * 8;
                ldsm_x4(a_hi[am], smem_u32(&Ph[r][cc]));
                ldsm_x4(a_lo[am], smem_u32(&Pl[r][cc]));
            }
#pragma unroll
            for (int pr = 0; pr < 4; pr++) {
                // trans: k-rows from (i&1), n-cols from (i>>1)  [see header]
                const int kr = ks + (lq & 1) * 8 + lr;
                const int nc = N0 + pr * 16 + (lq >> 1) * 8;
                uint32_t th[4], tl[4];
                ldsm_x4_t(th, smem_u32(&Vh[kr][nc]));
                ldsm_x4_t(tl, smem_u32(&Vl[kr][nc]));
#pragma unroll
                for (int am = 0; am < 2; am++) {
                    mma16816(acc[am][pr * 2 + 0], a_hi[am], th[0], th[1]);
                    mma16816(acc[am][pr * 2 + 1], a_hi[am], th[2], th[3]);
                    mma16816(acc[am][pr * 2 + 0], a_lo[am], th[0], th[1]);
                    mma16816(acc[am][pr * 2 + 1], a_lo[am], th[2], th[3]);
                    mma16816(acc[am][pr * 2 + 0], a_hi[am], tl[0], tl[1]);
                    mma16816(acc[am][pr * 2 + 1], a_hi[am], tl[2], tl[3]);
                }
            }
        }
    }

    float* Op = g_Op[c] + (size_t)b * SEQ * HDIM;
    const int gr = lane >> 2;
    const int gc = (lane & 3) * 2;
#pragma unroll
    for (int am = 0; am < 2; am++)
#pragma unroll
        for (int nb = 0; nb < 8; nb++) {
            const int t = t0 + M0 + am * 16 + gr;
            const int h = N0 + nb * 8 + gc;
            *(float2*)(Op + (size_t)t * HDIM + h) =
                make_float2(acc[am][nb][0], acc[am][nb][1]);
            *(float2*)(Op + (size_t)(t + 8) * HDIM + h) =
                make_float2(acc[am][nb][2], acc[am][nb][3]);
        }
}

// =============================================================================
// Kernel D2: reduce split-K partials. nc(t) = t/512 + 1.
// =============================================================================
__global__ void __launch_bounds__(256) pv_reduce(float* __restrict__ O) {
    const int idx4 = blockIdx.x * 256 + threadIdx.x;
    const int t    = (idx4 * 4 / HDIM) % SEQ;
    const int nc   = t / 512 + 1;

    float4 r = *(const float4*)(&g_Op[0][(size_t)idx4 * 4]);
    for (int c = 1; c < nc; c++) {
        float4 p = *(const float4*)(&g_Op[c][(size_t)idx4 * 4]);
        r.x += p.x; r.y += p.y; r.z += p.z; r.w += p.w;
    }
    *(float4*)(O + (size_t)idx4 * 4) = r;
}

// =============================================================================
extern "C" void kernel_launch(void* const* d_in, const int* in_sizes, int n_in,
                              void* d_out, int out_size) {
    const float* x  = (const float*)d_in[0];
    const float* Wk = (const float*)d_in[1];
    const float* Wq = (const float*)d_in[2];
    const float* Wv = (const float*)d_in[3];
    float* out = (float*)d_out;

    qkv_mma<<<dim3((BATCH * SEQ) / 128, 3), 256>>>(x, Wk, Wq, Wv);
    scores_mma<<<dim3(SEQ / 128, SEQ / 128, BATCH), 256>>>();
    stats_part<<<dim3(SEQ / 256, TCH, BATCH), 256>>>();
    stats_combine<<<dim3(SEQ / 256, BATCH), 256>>>();
    pv_mma<<<dim3(NCHUNK, SEQ / 128, BATCH), 256>>>();
    pv_reduce<<<(BATCH * SEQ * HDIM / 4) / 256, 256>>>(out);
}